// round 1
// baseline (speedup 1.0000x reference)
#include <cuda_runtime.h>
#include <math.h>

// Problem constants
#define TOKENS 2048          // B*S = 4*512
#define HID 256              // hidden
#define NB 41                // bins per axis
#define CBIN 123             // 3*41 combined
#define OUTC (CBIN * HID)    // 31488
#define OUT_PER_TOKEN (NB * NB * NB)  // 68921

// ---------------------------------------------------------------------------
// Scratch: bin_emb = softplus(emb @ W^T + b), token-major [TOKENS][OUTC]
// 2048 * 31488 * 4B = 258 MB (device global scratch, allowed)
// ---------------------------------------------------------------------------
__device__ float g_bin[(size_t)TOKENS * OUTC];

// ---------------------------------------------------------------------------
// Packed fp32x2 helpers (Blackwell FFMA2 — only reachable via PTX)
// ---------------------------------------------------------------------------
__device__ __forceinline__ void fma2(unsigned long long& d,
                                     unsigned long long a,
                                     unsigned long long b) {
    asm("fma.rn.f32x2 %0, %1, %2, %0;" : "+l"(d) : "l"(a), "l"(b));
}
__device__ __forceinline__ unsigned long long mul2(unsigned long long a,
                                                   unsigned long long b) {
    unsigned long long d;
    asm("mul.rn.f32x2 %0, %1, %2;" : "=l"(d) : "l"(a), "l"(b));
    return d;
}
__device__ __forceinline__ float pair_sum(unsigned long long v) {
    float lo = __uint_as_float((unsigned)(v & 0xffffffffull));
    float hi = __uint_as_float((unsigned)(v >> 32));
    return lo + hi;
}

// ---------------------------------------------------------------------------
// Kernel 1: bin = softplus(W @ emb^T + b)
// M = OUTC (o), N = TOKENS (t), K = HID. Both inputs K-contiguous.
// 128x128 block tile, BK=16, 256 threads, 8x8 thread tile, f32x2 over k.
// ---------------------------------------------------------------------------
#define BM 128
#define BN 128
#define BK 16
#define APAD 20   // row stride in floats (80B, 16B aligned, spreads banks)

__global__ void __launch_bounds__(256, 1) gemm_softplus_kernel(
    const float* __restrict__ W, const float* __restrict__ emb,
    const float* __restrict__ bias)
{
    __shared__ float As[BM][APAD];  // W rows (o), k-contiguous
    __shared__ float Bs[BN][APAD];  // emb rows (t), k-contiguous

    const int bm = blockIdx.x * BM;   // o base
    const int bn = blockIdx.y * BN;   // t base
    const int tid = threadIdx.x;
    const int tx = tid & 15;          // o lane (0..15)
    const int ty = tid >> 4;          // t lane (0..15)
    const int lr = tid >> 2;          // loader row 0..63
    const int lc = (tid & 3) << 2;    // loader col {0,4,8,12}

    unsigned long long acc[8][8];
    #pragma unroll
    for (int i = 0; i < 8; i++)
        #pragma unroll
        for (int j = 0; j < 8; j++) acc[i][j] = 0ull;

    for (int k0 = 0; k0 < HID; k0 += BK) {
        #pragma unroll
        for (int r = 0; r < 2; r++) {
            float4 va = *(const float4*)(W + (size_t)(bm + lr + 64 * r) * HID + k0 + lc);
            *(float4*)&As[lr + 64 * r][lc] = va;
            float4 vb = *(const float4*)(emb + (size_t)(bn + lr + 64 * r) * HID + k0 + lc);
            *(float4*)&Bs[lr + 64 * r][lc] = vb;
        }
        __syncthreads();

        #pragma unroll
        for (int kk = 0; kk < BK; kk += 2) {
            unsigned long long a[8], bb[8];
            #pragma unroll
            for (int i = 0; i < 8; i++)
                a[i] = *(const unsigned long long*)&As[tx + 16 * i][kk];
            #pragma unroll
            for (int j = 0; j < 8; j++)
                bb[j] = *(const unsigned long long*)&Bs[ty + 16 * j][kk];
            #pragma unroll
            for (int i = 0; i < 8; i++)
                #pragma unroll
                for (int j = 0; j < 8; j++)
                    fma2(acc[i][j], a[i], bb[j]);
        }
        __syncthreads();
    }

    // Epilogue: + bias, softplus, store token-major
    #pragma unroll
    for (int j = 0; j < 8; j++) {
        const int t = bn + ty + 16 * j;
        float* dst = g_bin + (size_t)t * OUTC;
        #pragma unroll
        for (int i = 0; i < 8; i++) {
            const int o = bm + tx + 16 * i;
            float x = pair_sum(acc[i][j]) + bias[o];
            // numerically stable softplus: max(x,0) + log1p(exp(-|x|))
            float sp = fmaxf(x, 0.0f) + log1pf(expf(-fabsf(x)));
            dst[o] = sp;
        }
    }
}

// ---------------------------------------------------------------------------
// Kernel 2: per-token triple contraction
// logits[t, y*41*41 + x*41 + z] = exp(ls) * sum_h ex[x,h] ey[y,h] ez[z,h]
// One CTA per token, 256 threads. All 123x256 rows in SMEM (stride 129 ull
// = 258 floats: odd-in-"c" banking, 8B aligned). 4x4x4 register tile/thread.
// ---------------------------------------------------------------------------
#define ROWQ 129                       // row stride in ull (float2) units
#define SMEM2_BYTES (CBIN * ROWQ * 8)  // 126,936 B

__global__ void __launch_bounds__(256, 1) triple_product_kernel(
    const float* __restrict__ ls, float* __restrict__ out)
{
    extern __shared__ unsigned long long sm2[];  // [CBIN][ROWQ]
    const int t = blockIdx.x;
    const unsigned long long* src =
        (const unsigned long long*)(g_bin + (size_t)t * OUTC);

    for (int i = threadIdx.x; i < CBIN * (HID / 2); i += 256) {
        int c = i >> 7;          // / 128
        int hh = i & 127;
        sm2[c * ROWQ + hh] = src[c * (HID / 2) + hh];
    }
    __syncthreads();

    const float scale = expf(ls[0]);
    float* outT = out + (size_t)t * OUT_PER_TOKEN;

    // 11x11x11 tiles of 4x4x4 covering 41^3
    for (int tile = threadIdx.x; tile < 11 * 11 * 11; tile += 256) {
        const int tyI = tile / 121;
        const int rem = tile - tyI * 121;
        const int txI = rem / 11;
        const int tzI = rem - txI * 11;
        const int y0 = tyI * 4, x0 = txI * 4, z0 = tzI * 4;

        int ox[4], oy[4], oz[4];
        #pragma unroll
        for (int i = 0; i < 4; i++) {
            ox[i] = (min(x0 + i, NB - 1)) * ROWQ;            // ex rows: c in [0,41)
            oy[i] = (NB + min(y0 + i, NB - 1)) * ROWQ;       // ey rows: [41,82)
            oz[i] = (2 * NB + min(z0 + i, NB - 1)) * ROWQ;   // ez rows: [82,123)
        }

        unsigned long long acc[4][4][4];
        #pragma unroll
        for (int iy = 0; iy < 4; iy++)
            #pragma unroll
            for (int ix = 0; ix < 4; ix++)
                #pragma unroll
                for (int iz = 0; iz < 4; iz++) acc[iy][ix][iz] = 0ull;

        #pragma unroll 2
        for (int hh = 0; hh < HID / 2; hh++) {
            unsigned long long a[4], b[4], c[4];
            #pragma unroll
            for (int i = 0; i < 4; i++) {
                a[i] = sm2[ox[i] + hh];
                b[i] = sm2[oy[i] + hh];
                c[i] = sm2[oz[i] + hh];
            }
            #pragma unroll
            for (int ix = 0; ix < 4; ix++) {
                #pragma unroll
                for (int iz = 0; iz < 4; iz++) {
                    unsigned long long p = mul2(a[ix], c[iz]);
                    #pragma unroll
                    for (int iy = 0; iy < 4; iy++)
                        fma2(acc[iy][ix][iz], b[iy], p);
                }
            }
        }

        #pragma unroll
        for (int iy = 0; iy < 4; iy++) {
            const int y = y0 + iy;
            if (y < NB) {
                #pragma unroll
                for (int ix = 0; ix < 4; ix++) {
                    const int x = x0 + ix;
                    if (x < NB) {
                        #pragma unroll
                        for (int iz = 0; iz < 4; iz++) {
                            const int z = z0 + iz;
                            if (z < NB) {
                                outT[y * (NB * NB) + x * NB + z] =
                                    pair_sum(acc[iy][ix][iz]) * scale;
                            }
                        }
                    }
                }
            }
        }
    }
}

// ---------------------------------------------------------------------------
// Launch
// ---------------------------------------------------------------------------
extern "C" void kernel_launch(void* const* d_in, const int* in_sizes, int n_in,
                              void* d_out, int out_size)
{
    const float *emb = nullptr, *W = nullptr, *bias = nullptr, *ls = nullptr;
    // Identify inputs by element count (robust to metadata ordering).
    for (int i = 0; i < n_in; i++) {
        switch (in_sizes[i]) {
            case TOKENS * HID:   emb  = (const float*)d_in[i]; break;  // 524288
            case OUTC * HID:     W    = (const float*)d_in[i]; break;  // 8060928
            case OUTC:           bias = (const float*)d_in[i]; break;  // 31488
            case 1:              ls   = (const float*)d_in[i]; break;
            default: break;
        }
    }

    dim3 g1(OUTC / BM, TOKENS / BN);  // 246 x 16
    gemm_softplus_kernel<<<g1, 256>>>(W, emb, bias);

    cudaFuncSetAttribute(triple_product_kernel,
                         cudaFuncAttributeMaxDynamicSharedMemorySize,
                         SMEM2_BYTES);
    triple_product_kernel<<<TOKENS, 256, SMEM2_BYTES>>>(ls, (float*)d_out);
}

// round 5
// speedup vs baseline: 2.3877x; 2.3877x over previous
#include <cuda_runtime.h>
#include <cuda_bf16.h>
#include <math.h>
#include <stdint.h>

// Problem constants
#define TOKENS 2048
#define HID 256
#define NB 41
#define CBIN 123
#define OUTC (CBIN * HID)    // 31488
#define OPT (NB * NB * NB)   // 68921
#define NXZ (NB * NB)        // 1681

// Scratch: bin = softplus(emb @ W^T + b), token-major bf16
__device__ __nv_bfloat16 g_bin[(size_t)TOKENS * OUTC];

// ---------------------------------------------------------------------------
// fp32x2 helpers (stage 1)
// ---------------------------------------------------------------------------
__device__ __forceinline__ void fma2(unsigned long long& d,
                                     unsigned long long a,
                                     unsigned long long b) {
    asm("fma.rn.f32x2 %0, %1, %2, %0;" : "+l"(d) : "l"(a), "l"(b));
}
__device__ __forceinline__ float pair_sum(unsigned long long v) {
    float lo = __uint_as_float((unsigned)(v & 0xffffffffull));
    float hi = __uint_as_float((unsigned)(v >> 32));
    return lo + hi;
}

// ---------------------------------------------------------------------------
// Kernel 1: bin = softplus(W @ emb^T + b), fp32 compute, bf16 store
// ---------------------------------------------------------------------------
#define BM 128
#define BN 128
#define BK 16
#define APAD 20

__global__ void __launch_bounds__(256, 1) gemm_softplus_kernel(
    const float* __restrict__ W, const float* __restrict__ emb,
    const float* __restrict__ bias)
{
    __shared__ float As[BM][APAD];
    __shared__ float Bs[BN][APAD];

    const int bm = blockIdx.x * BM;
    const int bn = blockIdx.y * BN;
    const int tid = threadIdx.x;
    const int tx = tid & 15;
    const int ty = tid >> 4;
    const int lr = tid >> 2;
    const int lc = (tid & 3) << 2;

    unsigned long long acc[8][8];
    #pragma unroll
    for (int i = 0; i < 8; i++)
        #pragma unroll
        for (int j = 0; j < 8; j++) acc[i][j] = 0ull;

    for (int k0 = 0; k0 < HID; k0 += BK) {
        #pragma unroll
        for (int r = 0; r < 2; r++) {
            float4 va = *(const float4*)(W + (size_t)(bm + lr + 64 * r) * HID + k0 + lc);
            *(float4*)&As[lr + 64 * r][lc] = va;
            float4 vb = *(const float4*)(emb + (size_t)(bn + lr + 64 * r) * HID + k0 + lc);
            *(float4*)&Bs[lr + 64 * r][lc] = vb;
        }
        __syncthreads();

        #pragma unroll
        for (int kk = 0; kk < BK; kk += 2) {
            unsigned long long a[8], bb[8];
            #pragma unroll
            for (int i = 0; i < 8; i++)
                a[i] = *(const unsigned long long*)&As[tx + 16 * i][kk];
            #pragma unroll
            for (int j = 0; j < 8; j++)
                bb[j] = *(const unsigned long long*)&Bs[ty + 16 * j][kk];
            #pragma unroll
            for (int i = 0; i < 8; i++)
                #pragma unroll
                for (int j = 0; j < 8; j++)
                    fma2(acc[i][j], a[i], bb[j]);
        }
        __syncthreads();
    }

    #pragma unroll
    for (int j = 0; j < 8; j++) {
        const int t = bn + ty + 16 * j;
        __nv_bfloat16* dst = g_bin + (size_t)t * OUTC;
        #pragma unroll
        for (int i = 0; i < 8; i++) {
            const int o = bm + tx + 16 * i;
            float x = pair_sum(acc[i][j]) + bias[o];
            float sp = fmaxf(x, 0.0f) + log1pf(expf(-fabsf(x)));
            dst[o] = __float2bfloat16(sp);
        }
    }
}

// ---------------------------------------------------------------------------
// Stage 2: per-token triple contraction via warp-level mma.sync (bf16, f32 acc)
//   Job = (z-tile of 16, x): D[z, y] = sum_h (ez[z,h]*ex[x,h]) * ey[y,h]
//   A-frags formed in registers: ez fragment loads * ex broadcast (mul.bf16x2)
//   out[t, y*1681 + x*41 + z]
// ---------------------------------------------------------------------------
#define RS 132           // SMEM row stride in u32 (132 % 32 == 4 -> bank-spread)
#define EYB 41           // ey rows at 41..88 (41..81 data, 82..88 zero)
#define EZB 89           // ez rows at 89..136 (89..129 data, 130..136 zero)
#define SM2_U32 (137 * RS)
#define SM2_BYTES (SM2_U32 * 4)   // 72336

__device__ __forceinline__ uint32_t bmul2(uint32_t a, uint32_t b) {
    uint32_t d;
    asm("mul.bf16x2 %0, %1, %2;" : "=r"(d) : "r"(a), "r"(b));
    return d;
}
__device__ __forceinline__ void mma16816(float* d,
                                         uint32_t a0, uint32_t a1,
                                         uint32_t a2, uint32_t a3,
                                         uint32_t b0, uint32_t b1) {
    asm volatile(
        "mma.sync.aligned.m16n8k16.row.col.f32.bf16.bf16.f32 "
        "{%0,%1,%2,%3}, {%4,%5,%6,%7}, {%8,%9}, {%0,%1,%2,%3};"
        : "+f"(d[0]), "+f"(d[1]), "+f"(d[2]), "+f"(d[3])
        : "r"(a0), "r"(a1), "r"(a2), "r"(a3), "r"(b0), "r"(b1));
}

__global__ void __launch_bounds__(256, 3) triple_mma_kernel(
    const float* __restrict__ ls, float* __restrict__ out)
{
    extern __shared__ uint32_t sm[];
    const int tid = threadIdx.x;
    const int wid = tid >> 5;
    const int lid = tid & 31;
    const int rowin = lid >> 2;   // 0..7
    const int qc = lid & 3;       // 0..3
    const int t = blockIdx.x;

    // Load token's 123x256 bf16 rows into padded SMEM (uint4 = 8 bf16)
    const uint4* src = (const uint4*)(g_bin + (size_t)t * OUTC);
    for (int i = tid; i < CBIN * 32; i += 256) {
        const int c = i >> 5;
        const int j = i & 31;
        const int dr = c + (c >= 82 ? 7 : 0);  // shift ez region past ey pad
        *(uint4*)&sm[dr * RS + j * 4] = src[i];
    }
    // Zero pad rows: 82..88 (ey) and 130..136 (ez)
    for (int i = tid; i < 7 * RS; i += 256) {
        sm[82 * RS + i] = 0u;
        sm[130 * RS + i] = 0u;
    }
    __syncthreads();

    const float scale = expf(ls[0]);
    float* __restrict__ outT = out + (size_t)t * OPT;

    for (int j = wid; j < 3 * NB; j += 8) {
        const int zt = j / NB;
        const int x = j - zt * NB;
        const int z0 = zt * 16;

        float acc[6][4];
        #pragma unroll
        for (int g = 0; g < 6; g++)
            #pragma unroll
            for (int q = 0; q < 4; q++) acc[g][q] = 0.0f;

        const uint32_t* __restrict__ exrow = sm + x * RS;
        const uint32_t* __restrict__ ez0p = sm + (EZB + z0 + rowin) * RS;
        const uint32_t* __restrict__ ez1p = ez0p + 8 * RS;
        const uint32_t* __restrict__ eyp = sm + (EYB + rowin) * RS;

        #pragma unroll
        for (int k = 0; k < 16; k++) {
            const int c0 = k * 8 + qc;
            const int c1 = c0 + 4;
            const uint32_t ex0 = exrow[c0];
            const uint32_t ex1 = exrow[c1];
            const uint32_t a0 = bmul2(ez0p[c0], ex0);
            const uint32_t a1 = bmul2(ez1p[c0], ex0);
            const uint32_t a2 = bmul2(ez0p[c1], ex1);
            const uint32_t a3 = bmul2(ez1p[c1], ex1);
            #pragma unroll
            for (int g = 0; g < 6; g++) {
                const uint32_t b0 = eyp[g * 8 * RS + c0];
                const uint32_t b1 = eyp[g * 8 * RS + c1];
                mma16816(acc[g], a0, a1, a2, a3, b0, b1);
            }
        }

        // Store: d0=(zlo,y) d1=(zlo,y+1) d2=(zhi,y) d3=(zhi,y+1)
        const int zlo = z0 + rowin;      // always < 41
        const int zhi = zlo + 8;
        float* const obase = outT + x * NB;
        #pragma unroll
        for (int g = 0; g < 6; g++) {
            const int y = 8 * g + 2 * qc;
            if (y < NB) {
                obase[(size_t)y * NXZ + zlo] = acc[g][0] * scale;
                if (zhi < NB) obase[(size_t)y * NXZ + zhi] = acc[g][2] * scale;
            }
            if (y + 1 < NB) {
                obase[(size_t)(y + 1) * NXZ + zlo] = acc[g][1] * scale;
                if (zhi < NB) obase[(size_t)(y + 1) * NXZ + zhi] = acc[g][3] * scale;
            }
        }
    }
}

// ---------------------------------------------------------------------------
// Launch
// ---------------------------------------------------------------------------
extern "C" void kernel_launch(void* const* d_in, const int* in_sizes, int n_in,
                              void* d_out, int out_size)
{
    const float *emb = nullptr, *W = nullptr, *bias = nullptr, *ls = nullptr;
    for (int i = 0; i < n_in; i++) {
        switch (in_sizes[i]) {
            case TOKENS * HID:   emb  = (const float*)d_in[i]; break;
            case OUTC * HID:     W    = (const float*)d_in[i]; break;
            case OUTC:           bias = (const float*)d_in[i]; break;
            case 1:              ls   = (const float*)d_in[i]; break;
            default: break;
        }
    }

    dim3 g1(OUTC / BM, TOKENS / BN);
    gemm_softplus_kernel<<<g1, 256>>>(W, emb, bias);

    cudaFuncSetAttribute(triple_mma_kernel,
                         cudaFuncAttributeMaxDynamicSharedMemorySize,
                         SM2_BYTES);
    triple_mma_kernel<<<TOKENS, 256, SM2_BYTES>>>(ls, (float*)d_out);
}

// round 6
// speedup vs baseline: 4.2610x; 1.7846x over previous
#include <cuda_runtime.h>
#include <cuda_bf16.h>
#include <math.h>
#include <stdint.h>

// Problem constants
#define TOKENS 2048
#define HID 256
#define NB 41
#define CBIN 123
#define OUTC (CBIN * HID)    // 31488
#define OPT (NB * NB * NB)   // 68921
#define NXZ (NB * NB)        // 1681

// Scratch: bin = softplus(emb @ W^T + b), token-major bf16
__device__ __nv_bfloat16 g_bin[(size_t)TOKENS * OUTC];

// ---------------------------------------------------------------------------
// Stage 1: tf32 tensor-core GEMM + softplus + bf16 store
//   C[t, o] = softplus( sum_k emb[t,k] * W[o,k] + b[o] )
//   A = emb (row-major m16k8 frags), B = W (k-major rows = col-major B frags)
//   CTA tile 128(t) x 128(o), BK=16, double-buffered, 8 warps of 64x32.
// ---------------------------------------------------------------------------
#define S1_PAD 20   // row stride in u32; (20*r + c) % 32 unique for r<8,c<4

__device__ __forceinline__ uint32_t f2tf32(float f) {
    uint32_t u;
    asm("cvt.rna.tf32.f32 %0, %1;" : "=r"(u) : "f"(f));
    return u;
}
__device__ __forceinline__ void mma16808(float* d, const uint32_t* a,
                                         const uint32_t* b) {
    asm volatile(
        "mma.sync.aligned.m16n8k8.row.col.f32.tf32.tf32.f32 "
        "{%0,%1,%2,%3}, {%4,%5,%6,%7}, {%8,%9}, {%0,%1,%2,%3};"
        : "+f"(d[0]), "+f"(d[1]), "+f"(d[2]), "+f"(d[3])
        : "r"(a[0]), "r"(a[1]), "r"(a[2]), "r"(a[3]), "r"(b[0]), "r"(b[1]));
}
__device__ __forceinline__ float softplusf(float x) {
    return fmaxf(x, 0.0f) + log1pf(expf(-fabsf(x)));
}

__global__ void __launch_bounds__(256, 2) gemm_softplus_tf32(
    const float* __restrict__ W, const float* __restrict__ emb,
    const float* __restrict__ bias)
{
    __shared__ uint32_t As[2][128 * S1_PAD];  // emb tile (t-major, k contig)
    __shared__ uint32_t Bs[2][128 * S1_PAD];  // W tile (o-major, k contig)

    const int t0 = blockIdx.y * 128;
    const int o0 = blockIdx.x * 128;
    const int tid = threadIdx.x;
    const int wid = tid >> 5, lane = tid & 31;
    const int wm = (wid & 1) * 64;       // t offset of warp tile
    const int wn = (wid >> 1) * 32;      // o offset of warp tile
    const int r = lane >> 2, c = lane & 3;

    float acc[4][4][4];
    #pragma unroll
    for (int mt = 0; mt < 4; mt++)
        #pragma unroll
        for (int nt = 0; nt < 4; nt++)
            #pragma unroll
            for (int q = 0; q < 4; q++) acc[mt][nt][q] = 0.0f;

    float4 ra[2], rb[2];
    const int lrow0 = tid >> 2;               // rows for l=0: idx=tid
    const int lcol = (tid & 3) << 2;
    const int lrow1 = (tid + 256) >> 2;       // rows for l=1

    // prologue: load k0=0
    ra[0] = *(const float4*)(emb + (size_t)(t0 + lrow0) * HID + lcol);
    rb[0] = *(const float4*)(W   + (size_t)(o0 + lrow0) * HID + lcol);
    ra[1] = *(const float4*)(emb + (size_t)(t0 + lrow1) * HID + lcol);
    rb[1] = *(const float4*)(W   + (size_t)(o0 + lrow1) * HID + lcol);
    {
        uint4 va0 = {f2tf32(ra[0].x), f2tf32(ra[0].y), f2tf32(ra[0].z), f2tf32(ra[0].w)};
        uint4 vb0 = {f2tf32(rb[0].x), f2tf32(rb[0].y), f2tf32(rb[0].z), f2tf32(rb[0].w)};
        uint4 va1 = {f2tf32(ra[1].x), f2tf32(ra[1].y), f2tf32(ra[1].z), f2tf32(ra[1].w)};
        uint4 vb1 = {f2tf32(rb[1].x), f2tf32(rb[1].y), f2tf32(rb[1].z), f2tf32(rb[1].w)};
        *(uint4*)&As[0][lrow0 * S1_PAD + lcol] = va0;
        *(uint4*)&Bs[0][lrow0 * S1_PAD + lcol] = vb0;
        *(uint4*)&As[0][lrow1 * S1_PAD + lcol] = va1;
        *(uint4*)&Bs[0][lrow1 * S1_PAD + lcol] = vb1;
    }
    __syncthreads();

    #pragma unroll 1
    for (int it = 0; it < 16; it++) {
        const int cur = it & 1;
        if (it < 15) {
            const int k0 = (it + 1) * 16;
            ra[0] = *(const float4*)(emb + (size_t)(t0 + lrow0) * HID + k0 + lcol);
            rb[0] = *(const float4*)(W   + (size_t)(o0 + lrow0) * HID + k0 + lcol);
            ra[1] = *(const float4*)(emb + (size_t)(t0 + lrow1) * HID + k0 + lcol);
            rb[1] = *(const float4*)(W   + (size_t)(o0 + lrow1) * HID + k0 + lcol);
        }

        #pragma unroll
        for (int kk = 0; kk < 2; kk++) {
            const int kb = kk * 8;
            uint32_t a[4][4], b[4][2];
            #pragma unroll
            for (int mt = 0; mt < 4; mt++) {
                const uint32_t* p = &As[cur][(wm + mt * 16 + r) * S1_PAD + kb + c];
                a[mt][0] = p[0];
                a[mt][1] = p[8 * S1_PAD];
                a[mt][2] = p[4];
                a[mt][3] = p[8 * S1_PAD + 4];
            }
            #pragma unroll
            for (int nt = 0; nt < 4; nt++) {
                const uint32_t* p = &Bs[cur][(wn + nt * 8 + r) * S1_PAD + kb + c];
                b[nt][0] = p[0];
                b[nt][1] = p[4];
            }
            #pragma unroll
            for (int mt = 0; mt < 4; mt++)
                #pragma unroll
                for (int nt = 0; nt < 4; nt++)
                    mma16808(acc[mt][nt], a[mt], b[nt]);
        }

        if (it < 15) {
            const int nxt = cur ^ 1;
            uint4 va0 = {f2tf32(ra[0].x), f2tf32(ra[0].y), f2tf32(ra[0].z), f2tf32(ra[0].w)};
            uint4 vb0 = {f2tf32(rb[0].x), f2tf32(rb[0].y), f2tf32(rb[0].z), f2tf32(rb[0].w)};
            uint4 va1 = {f2tf32(ra[1].x), f2tf32(ra[1].y), f2tf32(ra[1].z), f2tf32(ra[1].w)};
            uint4 vb1 = {f2tf32(rb[1].x), f2tf32(rb[1].y), f2tf32(rb[1].z), f2tf32(rb[1].w)};
            *(uint4*)&As[nxt][lrow0 * S1_PAD + lcol] = va0;
            *(uint4*)&Bs[nxt][lrow0 * S1_PAD + lcol] = vb0;
            *(uint4*)&As[nxt][lrow1 * S1_PAD + lcol] = va1;
            *(uint4*)&Bs[nxt][lrow1 * S1_PAD + lcol] = vb1;
            __syncthreads();
        }
    }

    // Epilogue: +bias, softplus, pack bf16x2, store token-major
    uint32_t* gb = (uint32_t*)g_bin;
    #pragma unroll
    for (int mt = 0; mt < 4; mt++) {
        const int tA = t0 + wm + mt * 16 + r;
        const size_t row0 = (size_t)tA * (OUTC / 2);
        const size_t row1 = (size_t)(tA + 8) * (OUTC / 2);
        #pragma unroll
        for (int nt = 0; nt < 4; nt++) {
            const int o = o0 + wn + nt * 8 + 2 * c;
            const float2 bi = *(const float2*)(bias + o);
            float s0 = softplusf(acc[mt][nt][0] + bi.x);
            float s1 = softplusf(acc[mt][nt][1] + bi.y);
            float s2 = softplusf(acc[mt][nt][2] + bi.x);
            float s3 = softplusf(acc[mt][nt][3] + bi.y);
            __nv_bfloat162 p0 = __float22bfloat162_rn(make_float2(s0, s1));
            __nv_bfloat162 p1 = __float22bfloat162_rn(make_float2(s2, s3));
            gb[row0 + (o >> 1)] = *(uint32_t*)&p0;
            gb[row1 + (o >> 1)] = *(uint32_t*)&p1;
        }
    }
}

// ---------------------------------------------------------------------------
// Stage 2: per-token triple contraction via warp mma.sync (bf16, f32 acc)
//   Job = (z-tile of 16, x-pair): ey fragments amortized over 2 x values.
// ---------------------------------------------------------------------------
#define RS 132           // SMEM row stride in u32 (132 % 32 == 4)
#define EYB 41           // ey rows at 41..88 (82..88 zero pad)
#define EZB 89           // ez rows at 89..136 (130..136 zero pad)
#define SM2_U32 (137 * RS)
#define SM2_BYTES (SM2_U32 * 4)   // 72336

__device__ __forceinline__ uint32_t bmul2(uint32_t a, uint32_t b) {
    uint32_t d;
    asm("mul.bf16x2 %0, %1, %2;" : "=r"(d) : "r"(a), "r"(b));
    return d;
}
__device__ __forceinline__ void mma16816(float* d,
                                         uint32_t a0, uint32_t a1,
                                         uint32_t a2, uint32_t a3,
                                         uint32_t b0, uint32_t b1) {
    asm volatile(
        "mma.sync.aligned.m16n8k16.row.col.f32.bf16.bf16.f32 "
        "{%0,%1,%2,%3}, {%4,%5,%6,%7}, {%8,%9}, {%0,%1,%2,%3};"
        : "+f"(d[0]), "+f"(d[1]), "+f"(d[2]), "+f"(d[3])
        : "r"(a0), "r"(a1), "r"(a2), "r"(a3), "r"(b0), "r"(b1));
}

__global__ void __launch_bounds__(256, 2) triple_mma_kernel(
    const float* __restrict__ ls, float* __restrict__ out)
{
    extern __shared__ uint32_t sm[];
    const int tid = threadIdx.x;
    const int wid = tid >> 5;
    const int lid = tid & 31;
    const int rowin = lid >> 2;   // 0..7
    const int qc = lid & 3;       // 0..3
    const int t = blockIdx.x;

    // Load token's 123x256 bf16 rows into padded SMEM (uint4 = 8 bf16)
    const uint4* src = (const uint4*)(g_bin + (size_t)t * OUTC);
    for (int i = tid; i < CBIN * 32; i += 256) {
        const int cc = i >> 5;
        const int j = i & 31;
        const int dr = cc + (cc >= 82 ? 7 : 0);  // shift ez past ey pad
        *(uint4*)&sm[dr * RS + j * 4] = src[i];
    }
    for (int i = tid; i < 7 * RS; i += 256) {
        sm[82 * RS + i] = 0u;
        sm[130 * RS + i] = 0u;
    }
    __syncthreads();

    const float scale = expf(ls[0]);
    float* __restrict__ outT = out + (size_t)t * OPT;

    // 63 jobs: zt in 0..2 (z tiles of 16), xp in 0..20 (x pairs; xp=20 single)
    for (int j = wid; j < 63; j += 8) {
        const int zt = j / 21;
        const int xp = j - zt * 21;
        const int x0 = 2 * xp;
        const bool hasx1 = (x0 + 1 < NB);
        const int x1 = hasx1 ? (x0 + 1) : (NB - 1);
        const int z0 = zt * 16;

        float acc[2][6][4];
        #pragma unroll
        for (int xi = 0; xi < 2; xi++)
            #pragma unroll
            for (int g = 0; g < 6; g++)
                #pragma unroll
                for (int q = 0; q < 4; q++) acc[xi][g][q] = 0.0f;

        const uint32_t* __restrict__ ex0p = sm + x0 * RS;
        const uint32_t* __restrict__ ex1p = sm + x1 * RS;
        const uint32_t* __restrict__ ezA = sm + (EZB + z0 + rowin) * RS;
        const uint32_t* __restrict__ ezB = ezA + 8 * RS;
        const uint32_t* __restrict__ eyp = sm + (EYB + rowin) * RS;

        #pragma unroll
        for (int k = 0; k < 16; k++) {
            const int c0 = k * 8 + qc;
            const int c1 = c0 + 4;
            const uint32_t ez0 = ezA[c0], ez1 = ezB[c0];
            const uint32_t ez2 = ezA[c1], ez3 = ezB[c1];
            const uint32_t exa0 = ex0p[c0], exa1 = ex0p[c1];
            const uint32_t exb0 = ex1p[c0], exb1 = ex1p[c1];
            const uint32_t A00 = bmul2(ez0, exa0), A01 = bmul2(ez1, exa0);
            const uint32_t A02 = bmul2(ez2, exa1), A03 = bmul2(ez3, exa1);
            const uint32_t A10 = bmul2(ez0, exb0), A11 = bmul2(ez1, exb0);
            const uint32_t A12 = bmul2(ez2, exb1), A13 = bmul2(ez3, exb1);
            #pragma unroll
            for (int g = 0; g < 6; g++) {
                const uint32_t b0 = eyp[g * 8 * RS + c0];
                const uint32_t b1 = eyp[g * 8 * RS + c1];
                mma16816(acc[0][g], A00, A01, A02, A03, b0, b1);
                mma16816(acc[1][g], A10, A11, A12, A13, b0, b1);
            }
        }

        const int zlo = z0 + rowin;      // < 41 always (z0 <= 32, rowin <= 7)
        const int zhi = zlo + 8;
        #pragma unroll
        for (int xi = 0; xi < 2; xi++) {
            if (xi == 1 && !hasx1) break;
            const int x = xi ? x1 : x0;
            float* const obase = outT + x * NB;
            #pragma unroll
            for (int g = 0; g < 6; g++) {
                const int y = 8 * g + 2 * qc;
                if (y < NB) {
                    obase[(size_t)y * NXZ + zlo] = acc[xi][g][0] * scale;
                    if (zhi < NB) obase[(size_t)y * NXZ + zhi] = acc[xi][g][2] * scale;
                }
                if (y + 1 < NB) {
                    obase[(size_t)(y + 1) * NXZ + zlo] = acc[xi][g][1] * scale;
                    if (zhi < NB) obase[(size_t)(y + 1) * NXZ + zhi] = acc[xi][g][3] * scale;
                }
            }
        }
    }
}

// ---------------------------------------------------------------------------
// Launch
// ---------------------------------------------------------------------------
extern "C" void kernel_launch(void* const* d_in, const int* in_sizes, int n_in,
                              void* d_out, int out_size)
{
    const float *emb = nullptr, *W = nullptr, *bias = nullptr, *ls = nullptr;
    for (int i = 0; i < n_in; i++) {
        switch (in_sizes[i]) {
            case TOKENS * HID:   emb  = (const float*)d_in[i]; break;
            case OUTC * HID:     W    = (const float*)d_in[i]; break;
            case OUTC:           bias = (const float*)d_in[i]; break;
            case 1:              ls   = (const float*)d_in[i]; break;
            default: break;
        }
    }

    dim3 g1(OUTC / 128, TOKENS / 128);  // 246 x 16
    gemm_softplus_tf32<<<g1, 256>>>(W, emb, bias);

    cudaFuncSetAttribute(triple_mma_kernel,
                         cudaFuncAttributeMaxDynamicSharedMemorySize,
                         SM2_BYTES);
    triple_mma_kernel<<<TOKENS, 256, SM2_BYTES>>>(ls, (float*)d_out);
}